// round 6
// baseline (speedup 1.0000x reference)
#include <cuda_runtime.h>

// FastfoodTransform: out[b,j] = S[j]*FWHT1024_stack( G ∘ permute_P( FWHT1024_stack(B∘x) ) ) + bias[j]
// BATCH=16384, IN=IN_EXT=1024, NSTACK=4, OUT=4096.
//
// R6: R5 was latency-exposed (occ 12%, issue 23%, regs 234 -> 2 blocks/SM).
// Cut cached weights to the gather-critical pk+Gv only, force 4 blocks/SM
// (16 warps). B/S/bias reload per row via LDG.128 (L1-resident, off the
// critical chain). Transpose tiles use stride 36 so T1-write / T2-read are
// 128-bit (4x fewer MIO instructions, same wavefronts).

static __device__ __forceinline__ void fwht32(float v[32]) {
#pragma unroll
    for (int h = 1; h < 32; h <<= 1) {
#pragma unroll
        for (int base = 0; base < 32; base += 2 * h) {
#pragma unroll
            for (int r = 0; r < h; r++) {
                float a = v[base + r];
                float b = v[base + r + h];
                v[base + r]     = a + b;
                v[base + r + h] = a - b;
            }
        }
    }
}

#define ROWS_PER_BLOCK 4

extern "C" __global__ void __launch_bounds__(128, 4)
fastfood_kernel(const float* __restrict__ x,
                const float* __restrict__ B,
                const float* __restrict__ G,
                const float* __restrict__ S,
                const float* __restrict__ bias,
                const int*   __restrict__ P,
                float* __restrict__ out,
                int batch)
{
    // buf: block-wide permute staging. tbuf: per-warp 32x32 transpose tiles,
    // stride 36 => float4-aligned rows, conflict-free in both directions:
    //   write tb[36l + 4q..] (STS.128): per 8-lane phase banks 4l..4l+3 distinct
    //   read  tb[36k + l]    (LDS.32):  banks (4k+l)&31 distinct over lanes
    __shared__ float buf[4096];
    __shared__ float tbuf[4][1152];

    const int l = threadIdx.x & 31;       // lane
    const int w = threadIdx.x >> 5;       // warp == stack
    const int a0  = w * 1024 + 32 * l;    // layout-A base (32 contiguous elems)
    const int bse = w * 1024 + l;         // layout-B base (stride-32 elems)
    float* tb = tbuf[w];

    // ---- gather-critical weights in registers (once per block) ----
    int   pk[32];                          // permute indices, layout B
    float Gv[32];                          // G, layout B
#pragma unroll
    for (int k = 0; k < 32; k++) pk[k] = P[bse + 32 * k];   // coalesced
#pragma unroll
    for (int k = 0; k < 32; k++) Gv[k] = G[bse + 32 * k];   // coalesced

    const float4* B4 = reinterpret_cast<const float4*>(B + a0);
    const float4* S4 = reinterpret_cast<const float4*>(S + a0);
    const float4* b4 = reinterpret_cast<const float4*>(bias + a0);

    const int row0 = blockIdx.x * ROWS_PER_BLOCK;

    for (int i = 0; i < ROWS_PER_BLOCK; i++) {
        const int row = row0 + i;
        if (row >= batch) break;          // uniform across block

        float v[32];

        // ---- v = x .* B (layout A); B stays L1-resident across blocks ----
        {
            const float4* x4 = reinterpret_cast<const float4*>(x + (size_t)row * 1024 + 32 * l);
#pragma unroll
            for (int q = 0; q < 8; q++) {
                float4 xv = x4[q];
                float4 bv = B4[q];
                v[4*q+0] = xv.x * bv.x;
                v[4*q+1] = xv.y * bv.y;
                v[4*q+2] = xv.z * bv.z;
                v[4*q+3] = xv.w * bv.w;
            }
        }

        // ---- FWHT #1, bits 0..4 ----
        fwht32(v);

        // ---- transpose A -> B (write 128-bit, read 32-bit) ----
        __syncwarp();                     // prior-row tb reads complete
        {
            float4* t4 = reinterpret_cast<float4*>(tb + 36 * l);
#pragma unroll
            for (int q = 0; q < 8; q++)
                t4[q] = make_float4(v[4*q+0], v[4*q+1], v[4*q+2], v[4*q+3]);
        }
        __syncwarp();
#pragma unroll
        for (int k = 0; k < 32; k++) v[k] = tb[36 * k + l];

        // ---- FWHT #1, bits 5..9 ----
        fwht32(v);

        // ---- stage full FWHT1 result for the cross-warp permutation ----
        __syncthreads();                  // prior-row gathers complete
#pragma unroll
        for (int k = 0; k < 32; k++) buf[w * 1024 + 32 * k + l] = v[k];  // bank=l
        __syncthreads();                  // buf fully written

        // ---- permuted gather ∘ G (layout B) ----
#pragma unroll
        for (int k = 0; k < 32; k++) v[k] = buf[pk[k]];
#pragma unroll
        for (int k = 0; k < 32; k++) v[k] *= Gv[k];

        // ---- FWHT #2, bits 5..9 ----
        fwht32(v);

        // ---- transpose B -> A (write 32-bit, read 128-bit) ----
        __syncwarp();
#pragma unroll
        for (int k = 0; k < 32; k++) tb[36 * k + l] = v[k];
        __syncwarp();
        {
            const float4* t4 = reinterpret_cast<const float4*>(tb + 36 * l);
#pragma unroll
            for (int q = 0; q < 8; q++) {
                float4 t = t4[q];
                v[4*q+0] = t.x; v[4*q+1] = t.y; v[4*q+2] = t.z; v[4*q+3] = t.w;
            }
        }

        // ---- FWHT #2, bits 0..4 ----
        fwht32(v);

        // ---- epilogue: S*v + bias (S/bias L1-resident), 128-bit store ----
        {
            float4* o4 = reinterpret_cast<float4*>(out + (size_t)row * 4096 + a0);
#pragma unroll
            for (int q = 0; q < 8; q++) {
                float4 sv = S4[q];
                float4 bb = b4[q];
                float4 ov;
                ov.x = fmaf(sv.x, v[4*q+0], bb.x);
                ov.y = fmaf(sv.y, v[4*q+1], bb.y);
                ov.z = fmaf(sv.z, v[4*q+2], bb.z);
                ov.w = fmaf(sv.w, v[4*q+3], bb.w);
                o4[q] = ov;
            }
        }
    }
}

extern "C" void kernel_launch(void* const* d_in, const int* in_sizes, int n_in,
                              void* d_out, int out_size)
{
    const float* x    = (const float*)d_in[0];   // (16384, 1024) f32
    const float* B    = (const float*)d_in[1];   // (4, 1024) f32
    const float* G    = (const float*)d_in[2];   // (4, 1024) f32
    const float* S    = (const float*)d_in[3];   // (4, 1024) f32
    const float* bias = (const float*)d_in[4];   // (4096,) f32
    const int*   P    = (const int*)d_in[5];     // (4096,) i32
    float* out = (float*)d_out;

    const int batch = in_sizes[0] / 1024;        // 16384
    const int grid  = (batch + ROWS_PER_BLOCK - 1) / ROWS_PER_BLOCK;
    fastfood_kernel<<<grid, 128>>>(x, B, G, S, bias, P, out, batch);
}

// round 7
// speedup vs baseline: 1.0141x; 1.0141x over previous
#include <cuda_runtime.h>

// FastfoodTransform: out[b,j] = S[j]*FWHT1024_stack( G ∘ permute_P( FWHT1024_stack(B∘x) ) ) + bias[j]
// BATCH=16384, IN=IN_EXT=1024, NSTACK=4, OUT=4096.
//
// R7: R6's (128,4) cap spilled (~15-20 regs) into local memory -> L1tex burned
// on LDL/STL, 394us. Fix: (128,3) => 168-reg cap. Named live set is only
// v[32]+pk[32]+Gv[32]=96, so no spills, and we get 12 warps/SM vs R5's 8.
// B/S/bias are reloaded per row via LDG.128 (L1-resident, off the critical
// chain). ROWS_PER_BLOCK=8 restores weight-load amortization.

static __device__ __forceinline__ void fwht32(float v[32]) {
#pragma unroll
    for (int h = 1; h < 32; h <<= 1) {
#pragma unroll
        for (int base = 0; base < 32; base += 2 * h) {
#pragma unroll
            for (int r = 0; r < h; r++) {
                float a = v[base + r];
                float b = v[base + r + h];
                v[base + r]     = a + b;
                v[base + r + h] = a - b;
            }
        }
    }
}

#define ROWS_PER_BLOCK 8

extern "C" __global__ void __launch_bounds__(128, 3)
fastfood_kernel(const float* __restrict__ x,
                const float* __restrict__ B,
                const float* __restrict__ G,
                const float* __restrict__ S,
                const float* __restrict__ bias,
                const int*   __restrict__ P,
                float* __restrict__ out,
                int batch)
{
    // buf: block-wide permute staging. tbuf: per-warp 32x32 transpose tiles,
    // stride 36 => float4-aligned rows, conflict-free in both directions:
    //   write tb[36l + 4q..] (STS.128): per 8-lane phase banks 4l..4l+3 distinct
    //   read  tb[36k + l]    (LDS.32):  banks (4k+l)&31 distinct over lanes
    __shared__ float buf[4096];
    __shared__ float tbuf[4][1152];

    const int l = threadIdx.x & 31;       // lane
    const int w = threadIdx.x >> 5;       // warp == stack
    const int a0  = w * 1024 + 32 * l;    // layout-A base (32 contiguous elems)
    const int bse = w * 1024 + l;         // layout-B base (stride-32 elems)
    float* tb = tbuf[w];

    // ---- gather-critical weights in registers (once per block) ----
    int   pk[32];                          // permute indices, layout B
    float Gv[32];                          // G, layout B
#pragma unroll
    for (int k = 0; k < 32; k++) pk[k] = P[bse + 32 * k];   // coalesced
#pragma unroll
    for (int k = 0; k < 32; k++) Gv[k] = G[bse + 32 * k];   // coalesced

    const float4* B4 = reinterpret_cast<const float4*>(B + a0);
    const float4* S4 = reinterpret_cast<const float4*>(S + a0);
    const float4* b4 = reinterpret_cast<const float4*>(bias + a0);

    const int row0 = blockIdx.x * ROWS_PER_BLOCK;

    for (int i = 0; i < ROWS_PER_BLOCK; i++) {
        const int row = row0 + i;
        if (row >= batch) break;          // uniform across block

        float v[32];

        // ---- v = x .* B (layout A); B stays L1-resident across blocks ----
        {
            const float4* x4 = reinterpret_cast<const float4*>(x + (size_t)row * 1024 + 32 * l);
#pragma unroll
            for (int q = 0; q < 8; q++) {
                float4 xv = x4[q];
                float4 bv = B4[q];
                v[4*q+0] = xv.x * bv.x;
                v[4*q+1] = xv.y * bv.y;
                v[4*q+2] = xv.z * bv.z;
                v[4*q+3] = xv.w * bv.w;
            }
        }

        // ---- FWHT #1, bits 0..4 ----
        fwht32(v);

        // ---- transpose A -> B (write 128-bit, read 32-bit) ----
        __syncwarp();                     // prior-row tb reads complete
        {
            float4* t4 = reinterpret_cast<float4*>(tb + 36 * l);
#pragma unroll
            for (int q = 0; q < 8; q++)
                t4[q] = make_float4(v[4*q+0], v[4*q+1], v[4*q+2], v[4*q+3]);
        }
        __syncwarp();
#pragma unroll
        for (int k = 0; k < 32; k++) v[k] = tb[36 * k + l];

        // ---- FWHT #1, bits 5..9 ----
        fwht32(v);

        // ---- stage full FWHT1 result for the cross-warp permutation ----
        __syncthreads();                  // prior-row gathers complete
#pragma unroll
        for (int k = 0; k < 32; k++) buf[w * 1024 + 32 * k + l] = v[k];  // bank=l
        __syncthreads();                  // buf fully written

        // ---- permuted gather ∘ G (layout B) ----
#pragma unroll
        for (int k = 0; k < 32; k++) v[k] = buf[pk[k]];
#pragma unroll
        for (int k = 0; k < 32; k++) v[k] *= Gv[k];

        // ---- FWHT #2, bits 5..9 ----
        fwht32(v);

        // ---- transpose B -> A (write 32-bit, read 128-bit) ----
        __syncwarp();
#pragma unroll
        for (int k = 0; k < 32; k++) tb[36 * k + l] = v[k];
        __syncwarp();
        {
            const float4* t4 = reinterpret_cast<const float4*>(tb + 36 * l);
#pragma unroll
            for (int q = 0; q < 8; q++) {
                float4 t = t4[q];
                v[4*q+0] = t.x; v[4*q+1] = t.y; v[4*q+2] = t.z; v[4*q+3] = t.w;
            }
        }

        // ---- FWHT #2, bits 0..4 ----
        fwht32(v);

        // ---- epilogue: S*v + bias (S/bias L1-resident), 128-bit store ----
        {
            float4* o4 = reinterpret_cast<float4*>(out + (size_t)row * 4096 + a0);
#pragma unroll
            for (int q = 0; q < 8; q++) {
                float4 sv = S4[q];
                float4 bb = b4[q];
                float4 ov;
                ov.x = fmaf(sv.x, v[4*q+0], bb.x);
                ov.y = fmaf(sv.y, v[4*q+1], bb.y);
                ov.z = fmaf(sv.z, v[4*q+2], bb.z);
                ov.w = fmaf(sv.w, v[4*q+3], bb.w);
                o4[q] = ov;
            }
        }
    }
}

extern "C" void kernel_launch(void* const* d_in, const int* in_sizes, int n_in,
                              void* d_out, int out_size)
{
    const float* x    = (const float*)d_in[0];   // (16384, 1024) f32
    const float* B    = (const float*)d_in[1];   // (4, 1024) f32
    const float* G    = (const float*)d_in[2];   // (4, 1024) f32
    const float* S    = (const float*)d_in[3];   // (4, 1024) f32
    const float* bias = (const float*)d_in[4];   // (4096,) f32
    const int*   P    = (const int*)d_in[5];     // (4096,) i32
    float* out = (float*)d_out;

    const int batch = in_sizes[0] / 1024;        // 16384
    const int grid  = (batch + ROWS_PER_BLOCK - 1) / ROWS_PER_BLOCK;
    fastfood_kernel<<<grid, 128>>>(x, B, G, S, bias, P, out, batch);
}

// round 10
// speedup vs baseline: 1.4354x; 1.4155x over previous
#include <cuda_runtime.h>

// FastfoodTransform: out[b,j] = S[j]*FWHT1024_stack( G ∘ permute_P( FWHT1024_stack(B∘x) ) ) + bias[j]
// BATCH=16384, IN=IN_EXT=1024, NSTACK=4, OUT=4096.
//
// R8: reg-cap experiments (R6/R7) proved occupancy can't be bought without
// spills; R5 (233us, 8 warps/SM) was latency-exposed (issue 23%). This round
// buys ILP instead: each warp carries TWO rows through the pipeline with
// interleaved instruction streams, so row1's FADDs cover row0's LDS/LDG
// latencies and the random gather runs at 64 outstanding LDS. Barriers are
// per-pair. Weights: pk+Gv register-cached (used by both rows); B/S/bias
// loaded once per pair as transients and used twice.
//
// Layouts per warp (stack w), per row:
//   A: lane l holds elems [32l,32l+32)  -> fwht32 = FWHT bits 0..4
//   stride-36 padded per-warp transpose (conflict-free, float4 on one side)
//   B: lane l holds elems {l+32k}       -> fwht32 = FWHT bits 5..9

static __device__ __forceinline__ void fwht32(float v[32]) {
#pragma unroll
    for (int h = 1; h < 32; h <<= 1) {
#pragma unroll
        for (int base = 0; base < 32; base += 2 * h) {
#pragma unroll
            for (int r = 0; r < h; r++) {
                float a = v[base + r];
                float b = v[base + r + h];
                v[base + r]     = a + b;
                v[base + r + h] = a - b;
            }
        }
    }
}

#define ROWS_PER_BLOCK 8   // 4 pairs

extern "C" __global__ void __launch_bounds__(128, 2)
fastfood_kernel(const float* __restrict__ x,
                const float* __restrict__ B,
                const float* __restrict__ G,
                const float* __restrict__ S,
                const float* __restrict__ bias,
                const int*   __restrict__ P,
                float* __restrict__ out,
                int batch)
{
    // Dynamic shared: [0, 8192)       buf: two 4096-float permute buffers
    //                 [8192, 8192+9216) tbuf: 8 per-warp 1152-float tiles
    extern __shared__ float smem[];
    float* buf0 = smem;             // row0 permute staging
    float* buf1 = smem + 4096;      // row1 permute staging
    float* tb0  = smem + 8192 + (threadIdx.x >> 5) * 1152;          // row0 tile
    float* tb1  = smem + 8192 + 4 * 1152 + (threadIdx.x >> 5) * 1152; // row1 tile

    const int l = threadIdx.x & 31;       // lane
    const int w = threadIdx.x >> 5;       // warp == stack
    const int a0  = w * 1024 + 32 * l;    // layout-A base (32 contiguous elems)
    const int bse = w * 1024 + l;         // layout-B base (stride-32 elems)

    // ---- gather-critical weights, register-resident (once per block) ----
    int   pk[32];                          // permute indices, layout B
    float Gv[32];                          // G, layout B
#pragma unroll
    for (int k = 0; k < 32; k++) pk[k] = P[bse + 32 * k];   // coalesced
#pragma unroll
    for (int k = 0; k < 32; k++) Gv[k] = G[bse + 32 * k];   // coalesced

    const float4* B4 = reinterpret_cast<const float4*>(B + a0);
    const float4* S4 = reinterpret_cast<const float4*>(S + a0);
    const float4* b4 = reinterpret_cast<const float4*>(bias + a0);

    const int row0 = blockIdx.x * ROWS_PER_BLOCK;

#pragma unroll 1
    for (int i = 0; i < ROWS_PER_BLOCK; i += 2) {
        const int r0 = row0 + i;
        const int r1 = r0 + 1;           // batch is a multiple of ROWS_PER_BLOCK

        float v0[32], v1[32];

        // ---- v = x .* B for both rows (B float4 loaded once, used twice) ----
        {
            const float4* x40 = reinterpret_cast<const float4*>(x + (size_t)r0 * 1024 + 32 * l);
            const float4* x41 = reinterpret_cast<const float4*>(x + (size_t)r1 * 1024 + 32 * l);
#pragma unroll
            for (int q = 0; q < 8; q++) {
                float4 bv  = B4[q];
                float4 xa  = x40[q];
                float4 xb  = x41[q];
                v0[4*q+0] = xa.x * bv.x;  v1[4*q+0] = xb.x * bv.x;
                v0[4*q+1] = xa.y * bv.y;  v1[4*q+1] = xb.y * bv.y;
                v0[4*q+2] = xa.z * bv.z;  v1[4*q+2] = xb.z * bv.z;
                v0[4*q+3] = xa.w * bv.w;  v1[4*q+3] = xb.w * bv.w;
            }
        }

        // ---- FWHT #1, bits 0..4 (two independent streams) ----
        fwht32(v0);
        fwht32(v1);

        // ---- transpose A -> B, both rows (write 128-bit, read 32-bit) ----
        __syncwarp();                     // prior pair's tile reads complete
        {
            float4* t40 = reinterpret_cast<float4*>(tb0 + 36 * l);
            float4* t41 = reinterpret_cast<float4*>(tb1 + 36 * l);
#pragma unroll
            for (int q = 0; q < 8; q++) {
                t40[q] = make_float4(v0[4*q+0], v0[4*q+1], v0[4*q+2], v0[4*q+3]);
                t41[q] = make_float4(v1[4*q+0], v1[4*q+1], v1[4*q+2], v1[4*q+3]);
            }
        }
        __syncwarp();
#pragma unroll
        for (int k = 0; k < 32; k++) { v0[k] = tb0[36 * k + l]; v1[k] = tb1[36 * k + l]; }

        // ---- FWHT #1, bits 5..9 ----
        fwht32(v0);
        fwht32(v1);

        // ---- stage both FWHT1 results for the cross-warp permutation ----
        __syncthreads();                  // prior pair's gathers complete
#pragma unroll
        for (int k = 0; k < 32; k++) {
            buf0[w * 1024 + 32 * k + l] = v0[k];   // bank = l: conflict-free
            buf1[w * 1024 + 32 * k + l] = v1[k];
        }
        __syncthreads();                  // both buffers fully written

        // ---- permuted gather ∘ G, both rows (64 LDS in flight) ----
#pragma unroll
        for (int k = 0; k < 32; k++) { v0[k] = buf0[pk[k]]; v1[k] = buf1[pk[k]]; }
#pragma unroll
        for (int k = 0; k < 32; k++) { v0[k] *= Gv[k]; v1[k] *= Gv[k]; }

        // ---- FWHT #2, bits 5..9 ----
        fwht32(v0);
        fwht32(v1);

        // ---- transpose B -> A, both rows (write 32-bit, read 128-bit) ----
        __syncwarp();
#pragma unroll
        for (int k = 0; k < 32; k++) { tb0[36 * k + l] = v0[k]; tb1[36 * k + l] = v1[k]; }
        __syncwarp();
        {
            const float4* t40 = reinterpret_cast<const float4*>(tb0 + 36 * l);
            const float4* t41 = reinterpret_cast<const float4*>(tb1 + 36 * l);
#pragma unroll
            for (int q = 0; q < 8; q++) {
                float4 ta = t40[q];
                float4 tbq = t41[q];
                v0[4*q+0] = ta.x;  v0[4*q+1] = ta.y;  v0[4*q+2] = ta.z;  v0[4*q+3] = ta.w;
                v1[4*q+0] = tbq.x; v1[4*q+1] = tbq.y; v1[4*q+2] = tbq.z; v1[4*q+3] = tbq.w;
            }
        }

        // ---- FWHT #2, bits 0..4 ----
        fwht32(v0);
        fwht32(v1);

        // ---- epilogue: S*v + bias, both rows (S/bias loaded once) ----
        {
            float4* o40 = reinterpret_cast<float4*>(out + (size_t)r0 * 4096 + a0);
            float4* o41 = reinterpret_cast<float4*>(out + (size_t)r1 * 4096 + a0);
#pragma unroll
            for (int q = 0; q < 8; q++) {
                float4 sv = S4[q];
                float4 bb = b4[q];
                float4 oa, ob;
                oa.x = fmaf(sv.x, v0[4*q+0], bb.x);  ob.x = fmaf(sv.x, v1[4*q+0], bb.x);
                oa.y = fmaf(sv.y, v0[4*q+1], bb.y);  ob.y = fmaf(sv.y, v1[4*q+1], bb.y);
                oa.z = fmaf(sv.z, v0[4*q+2], bb.z);  ob.z = fmaf(sv.z, v1[4*q+2], bb.z);
                oa.w = fmaf(sv.w, v0[4*q+3], bb.w);  ob.w = fmaf(sv.w, v1[4*q+3], bb.w);
                o40[q] = oa;
                o41[q] = ob;
            }
        }
    }
}

extern "C" void kernel_launch(void* const* d_in, const int* in_sizes, int n_in,
                              void* d_out, int out_size)
{
    const float* x    = (const float*)d_in[0];   // (16384, 1024) f32
    const float* B    = (const float*)d_in[1];   // (4, 1024) f32
    const float* G    = (const float*)d_in[2];   // (4, 1024) f32
    const float* S    = (const float*)d_in[3];   // (4, 1024) f32
    const float* bias = (const float*)d_in[4];   // (4096,) f32
    const int*   P    = (const int*)d_in[5];     // (4096,) i32
    float* out = (float*)d_out;

    const int batch = in_sizes[0] / 1024;        // 16384

    // 2*4096 (permute bufs) + 8*1152 (transpose tiles) floats = 68 KB
    const int smem_bytes = (2 * 4096 + 8 * 1152) * (int)sizeof(float);
    static int configured = 0;
    if (!configured) {
        cudaFuncSetAttribute(fastfood_kernel,
                             cudaFuncAttributeMaxDynamicSharedMemorySize, smem_bytes);
        configured = 1;
    }

    const int grid = (batch + ROWS_PER_BLOCK - 1) / ROWS_PER_BLOCK;
    fastfood_kernel<<<grid, 128, smem_bytes>>>(x, B, G, S, bias, P, out, batch);
}

// round 11
// speedup vs baseline: 2.2823x; 1.5899x over previous
#include <cuda_runtime.h>

// FastfoodTransform: out[b,j] = S[j]*FWHT1024_stack( G ∘ permute_P( FWHT1024_stack(B∘x) ) ) + bias[j]
// BATCH=16384, IN=IN_EXT=1024, NSTACK=4, OUT=4096.
//
// R11: R5's 192-named-reg envelope (proven no-spill at 234 regs, (128,2)) +
//  (1) cp.async (LDGSTS, register-free) double-buffered x prefetch: DRAM
//      latency off the row-critical path; x consumed via swizzled LDS.128.
//  (2) permute staging as 8x STS.128 into an XOR-swizzled layout-B-linear
//      buffer; the swizzle+layout remap is folded into pk at block setup.
//  (3) stride-36 float4 transpose tiles (T1 write / T2 read 128-bit).
// Reg-cap lessons R6/R7/R8: never exceed the natural ~234; no launch_bounds
// below (128,2).

static __device__ __forceinline__ void fwht32(float v[32]) {
#pragma unroll
    for (int h = 1; h < 32; h <<= 1) {
#pragma unroll
        for (int base = 0; base < 32; base += 2 * h) {
#pragma unroll
            for (int r = 0; r < h; r++) {
                float a = v[base + r];
                float b = v[base + r + h];
                v[base + r]     = a + b;
                v[base + r + h] = a - b;
            }
        }
    }
}

static __device__ __forceinline__ void cp_async16(unsigned saddr, const void* g) {
    asm volatile("cp.async.cg.shared.global [%0], [%1], 16;" :: "r"(saddr), "l"(g));
}

#define ROWS_PER_BLOCK 8

extern "C" __global__ void __launch_bounds__(128, 2)
fastfood_kernel(const float* __restrict__ x,
                const float* __restrict__ B,
                const float* __restrict__ G,
                const float* __restrict__ S,
                const float* __restrict__ bias,
                const int*   __restrict__ P,
                float* __restrict__ out,
                int batch)
{
    // buf : 4096-float permute staging, layout-B-linear + float4 XOR swizzle.
    // tbuf: per-warp 32x32 transpose tiles, stride 36 (conflict-free, float4
    //       on the contiguous side).
    // xbuf: double-buffered x row (1024 floats), float4 XOR swizzle.
    __shared__ float buf[4096];
    __shared__ float tbuf[4][1152];
    __shared__ float xbuf[2][1024];

    const int t = threadIdx.x;
    const int l = t & 31;                 // lane
    const int w = t >> 5;                 // warp == stack
    const int a0  = w * 1024 + 32 * l;    // layout-A base (32 contiguous elems)
    const int bse = w * 1024 + l;         // layout-B base (stride-32 elems)
    float* tb = tbuf[w];

    // ---- register-resident weights (once per block; R5 envelope) ----
    float Bv[32], Sv[32], Biv[32];        // layout A
    float Gv[32];                         // layout B
    int   pk[32];                         // gather addr into swizzled buf
    {
        const float4* B4 = reinterpret_cast<const float4*>(B + a0);
        const float4* S4 = reinterpret_cast<const float4*>(S + a0);
        const float4* b4 = reinterpret_cast<const float4*>(bias + a0);
#pragma unroll
        for (int q = 0; q < 8; q++) {
            float4 tv;
            tv = B4[q]; Bv[4*q+0]=tv.x; Bv[4*q+1]=tv.y; Bv[4*q+2]=tv.z; Bv[4*q+3]=tv.w;
            tv = S4[q]; Sv[4*q+0]=tv.x; Sv[4*q+1]=tv.y; Sv[4*q+2]=tv.z; Sv[4*q+3]=tv.w;
            tv = b4[q]; Biv[4*q+0]=tv.x; Biv[4*q+1]=tv.y; Biv[4*q+2]=tv.z; Biv[4*q+3]=tv.w;
        }
#pragma unroll
        for (int k = 0; k < 32; k++) Gv[k] = G[bse + 32 * k];   // coalesced
#pragma unroll
        for (int k = 0; k < 32; k++) {
            int raw   = P[bse + 32 * k];                 // element in [0,4096)
            int stack = raw >> 10;
            int off   = raw & 1023;
            int iB    = ((off & 31) << 5) | (off >> 5);  // layout-B-linear
            int c     = iB >> 2;                         // float4 chunk
            int p     = c ^ ((c >> 3) & 7);              // XOR swizzle
            pk[k]     = (stack << 10) | (p << 2) | (iB & 3);
        }
    }

    const int row0 = blockIdx.x * ROWS_PER_BLOCK;

    // ---- prologue: prefetch row0's x (thread t owns chunks 2t, 2t+1) ----
    {
        int rr = (row0 < batch) ? row0 : (batch - 1);
        const float* gx = x + (size_t)rr * 1024 + t * 8;
        unsigned sb = (unsigned)__cvta_generic_to_shared(&xbuf[0][0]);
        int c0 = 2 * t, c1 = 2 * t + 1;
        cp_async16(sb + (unsigned)((c0 ^ ((c0 >> 3) & 7)) * 16), gx);
        cp_async16(sb + (unsigned)((c1 ^ ((c1 >> 3) & 7)) * 16), gx + 4);
        asm volatile("cp.async.commit_group;" ::: "memory");
    }

#pragma unroll 1
    for (int i = 0; i < ROWS_PER_BLOCK; i++) {
        const int row = row0 + i;

        asm volatile("cp.async.wait_group 0;" ::: "memory");
        __syncthreads();                  // xbuf[i&1] visible; prior gathers done

        // ---- prefetch next row's x into the other slot ----
        if (i + 1 < ROWS_PER_BLOCK) {
            int rn = row + 1;
            int rr = (rn < batch) ? rn : (batch - 1);
            const float* gx = x + (size_t)rr * 1024 + t * 8;
            unsigned sb = (unsigned)__cvta_generic_to_shared(&xbuf[(i + 1) & 1][0]);
            int c0 = 2 * t, c1 = 2 * t + 1;
            cp_async16(sb + (unsigned)((c0 ^ ((c0 >> 3) & 7)) * 16), gx);
            cp_async16(sb + (unsigned)((c1 ^ ((c1 >> 3) & 7)) * 16), gx + 4);
        }
        asm volatile("cp.async.commit_group;" ::: "memory");

        float v[32];

        // ---- v = x .* B  (swizzled LDS.128, conflict-free) ----
        {
            const float* xs = xbuf[i & 1];
#pragma unroll
            for (int q = 0; q < 8; q++) {
                float4 xv = *reinterpret_cast<const float4*>(
                    xs + 32 * l + 4 * (q ^ (l & 7)));
                v[4*q+0] = xv.x * Bv[4*q+0];
                v[4*q+1] = xv.y * Bv[4*q+1];
                v[4*q+2] = xv.z * Bv[4*q+2];
                v[4*q+3] = xv.w * Bv[4*q+3];
            }
        }

        // ---- FWHT #1, bits 0..4 ----
        fwht32(v);

        // ---- transpose A -> B (write 128-bit, read 32-bit) ----
        __syncwarp();
        {
            float4* t4 = reinterpret_cast<float4*>(tb + 36 * l);
#pragma unroll
            for (int q = 0; q < 8; q++)
                t4[q] = make_float4(v[4*q+0], v[4*q+1], v[4*q+2], v[4*q+3]);
        }
        __syncwarp();
#pragma unroll
        for (int k = 0; k < 32; k++) v[k] = tb[36 * k + l];

        // ---- FWHT #1, bits 5..9 ----
        fwht32(v);

        // ---- stage to buf: layout-B-linear + swizzle, 8x STS.128 ----
        {
            float* bw = buf + w * 1024;
#pragma unroll
            for (int q = 0; q < 8; q++) {
                int p = 8 * l + (q ^ (l & 7));
                *reinterpret_cast<float4*>(bw + 4 * p) =
                    make_float4(v[4*q+0], v[4*q+1], v[4*q+2], v[4*q+3]);
            }
        }
        __syncthreads();                  // buf fully written

        // ---- permuted gather ∘ G (layout B) ----
#pragma unroll
        for (int k = 0; k < 32; k++) v[k] = buf[pk[k]];
#pragma unroll
        for (int k = 0; k < 32; k++) v[k] *= Gv[k];

        // ---- FWHT #2, bits 5..9 ----
        fwht32(v);

        // ---- transpose B -> A (write 32-bit, read 128-bit) ----
        __syncwarp();
#pragma unroll
        for (int k = 0; k < 32; k++) tb[36 * k + l] = v[k];
        __syncwarp();
        {
            const float4* t4 = reinterpret_cast<const float4*>(tb + 36 * l);
#pragma unroll
            for (int q = 0; q < 8; q++) {
                float4 tv = t4[q];
                v[4*q+0] = tv.x; v[4*q+1] = tv.y; v[4*q+2] = tv.z; v[4*q+3] = tv.w;
            }
        }

        // ---- FWHT #2, bits 0..4 ----
        fwht32(v);

        // ---- epilogue: S*v + bias, 128-bit store ----
        if (row < batch) {
            float4* o4 = reinterpret_cast<float4*>(out + (size_t)row * 4096 + a0);
#pragma unroll
            for (int q = 0; q < 8; q++) {
                float4 ov;
                ov.x = fmaf(Sv[4*q+0], v[4*q+0], Biv[4*q+0]);
                ov.y = fmaf(Sv[4*q+1], v[4*q+1], Biv[4*q+1]);
                ov.z = fmaf(Sv[4*q+2], v[4*q+2], Biv[4*q+2]);
                ov.w = fmaf(Sv[4*q+3], v[4*q+3], Biv[4*q+3]);
                o4[q] = ov;
            }
        }
    }
}

extern "C" void kernel_launch(void* const* d_in, const int* in_sizes, int n_in,
                              void* d_out, int out_size)
{
    const float* x    = (const float*)d_in[0];   // (16384, 1024) f32
    const float* B    = (const float*)d_in[1];   // (4, 1024) f32
    const float* G    = (const float*)d_in[2];   // (4, 1024) f32
    const float* S    = (const float*)d_in[3];   // (4, 1024) f32
    const float* bias = (const float*)d_in[4];   // (4096,) f32
    const int*   P    = (const int*)d_in[5];     // (4096,) i32
    float* out = (float*)d_out;

    const int batch = in_sizes[0] / 1024;        // 16384
    const int grid  = (batch + ROWS_PER_BLOCK - 1) / ROWS_PER_BLOCK;
    fastfood_kernel<<<grid, 128>>>(x, B, G, S, bias, P, out, batch);
}

// round 14
// speedup vs baseline: 2.2886x; 1.0028x over previous
#include <cuda_runtime.h>

// FastfoodTransform: out[b,j] = S[j]*FWHT1024_stack( G ∘ permute_P( FWHT1024_stack(B∘x) ) ) + bias[j]
// BATCH=16384, IN=IN_EXT=1024, NSTACK=4, OUT=4096.
//
// R12 = R11 (cp.async x prefetch, swizzled layout-B staging, stride-36 float4
// transpose tiles, pk/Gv/Bv/Sv/Biv register weights, (128,2)) + packed-f32x2
// FWHT: stage h=1 scalar, stages h=2..16 on 16 packed 64-bit regs
// (add.rn.f32x2 / fma.rn.f32x2 with -1 multiplier => exact a-b).
// Reg-cap lessons R6/R7/R8: never cap below (128,2); natural regs ~254.

static __device__ __forceinline__ void fwht32p(float v[32]) {
    unsigned long long p[16];
    const unsigned long long M1 = 0xBF800000BF800000ULL;  // packed (-1.f,-1.f)
    // stage h=1 (scalar) fused with pack
#pragma unroll
    for (int j = 0; j < 16; j++) {
        float a = v[2*j], b = v[2*j+1];
        float s = a + b, d = a - b;
        asm("mov.b64 %0, {%1,%2};" : "=l"(p[j]) : "f"(s), "f"(d));
    }
    // stages h=2,4,8,16  ==  packed hp=1,2,4,8
#pragma unroll
    for (int hp = 1; hp < 16; hp <<= 1) {
#pragma unroll
        for (int base = 0; base < 16; base += 2 * hp) {
#pragma unroll
            for (int r = 0; r < hp; r++) {
                unsigned long long A = p[base + r];
                unsigned long long Bp = p[base + r + hp];
                unsigned long long s, d;
                asm("add.rn.f32x2 %0, %1, %2;"     : "=l"(s) : "l"(A), "l"(Bp));
                asm("fma.rn.f32x2 %0, %1, %2, %3;" : "=l"(d) : "l"(Bp), "l"(M1), "l"(A));
                p[base + r]      = s;
                p[base + r + hp] = d;
            }
        }
    }
#pragma unroll
    for (int j = 0; j < 16; j++)
        asm("mov.b64 {%0,%1}, %2;" : "=f"(v[2*j]), "=f"(v[2*j+1]) : "l"(p[j]));
}

static __device__ __forceinline__ void cp_async16(unsigned saddr, const void* g) {
    asm volatile("cp.async.cg.shared.global [%0], [%1], 16;" :: "r"(saddr), "l"(g));
}

#define ROWS_PER_BLOCK 8

extern "C" __global__ void __launch_bounds__(128, 2)
fastfood_kernel(const float* __restrict__ x,
                const float* __restrict__ B,
                const float* __restrict__ G,
                const float* __restrict__ S,
                const float* __restrict__ bias,
                const int*   __restrict__ P,
                float* __restrict__ out,
                int batch)
{
    // buf : 4096-float permute staging, layout-B-linear + float4 XOR swizzle.
    // tbuf: per-warp 32x32 transpose tiles, stride 36 (conflict-free, float4
    //       on the contiguous side).
    // xbuf: double-buffered x row (1024 floats), float4 XOR swizzle.
    __shared__ float buf[4096];
    __shared__ float tbuf[4][1152];
    __shared__ float xbuf[2][1024];

    const int t = threadIdx.x;
    const int l = t & 31;                 // lane
    const int w = t >> 5;                 // warp == stack
    const int a0  = w * 1024 + 32 * l;    // layout-A base (32 contiguous elems)
    const int bse = w * 1024 + l;         // layout-B base (stride-32 elems)
    float* tb = tbuf[w];

    // ---- register-resident weights (once per block) ----
    float Bv[32], Sv[32], Biv[32];        // layout A
    float Gv[32];                         // layout B
    int   pk[32];                         // gather addr into swizzled buf
    {
        const float4* B4 = reinterpret_cast<const float4*>(B + a0);
        const float4* S4 = reinterpret_cast<const float4*>(S + a0);
        const float4* b4 = reinterpret_cast<const float4*>(bias + a0);
#pragma unroll
        for (int q = 0; q < 8; q++) {
            float4 tv;
            tv = B4[q]; Bv[4*q+0]=tv.x; Bv[4*q+1]=tv.y; Bv[4*q+2]=tv.z; Bv[4*q+3]=tv.w;
            tv = S4[q]; Sv[4*q+0]=tv.x; Sv[4*q+1]=tv.y; Sv[4*q+2]=tv.z; Sv[4*q+3]=tv.w;
            tv = b4[q]; Biv[4*q+0]=tv.x; Biv[4*q+1]=tv.y; Biv[4*q+2]=tv.z; Biv[4*q+3]=tv.w;
        }
#pragma unroll
        for (int k = 0; k < 32; k++) Gv[k] = G[bse + 32 * k];   // coalesced
#pragma unroll
        for (int k = 0; k < 32; k++) {
            int raw   = P[bse + 32 * k];                 // element in [0,4096)
            int stack = raw >> 10;
            int off   = raw & 1023;
            int iB    = ((off & 31) << 5) | (off >> 5);  // layout-B-linear
            int c     = iB >> 2;                         // float4 chunk
            int p     = c ^ ((c >> 3) & 7);              // XOR swizzle
            pk[k]     = (stack << 10) | (p << 2) | (iB & 3);
        }
    }

    const int row0 = blockIdx.x * ROWS_PER_BLOCK;

    // ---- prologue: prefetch row0's x (thread t owns chunks 2t, 2t+1) ----
    {
        int rr = (row0 < batch) ? row0 : (batch - 1);
        const float* gx = x + (size_t)rr * 1024 + t * 8;
        unsigned sb = (unsigned)__cvta_generic_to_shared(&xbuf[0][0]);
        int c0 = 2 * t, c1 = 2 * t + 1;
        cp_async16(sb + (unsigned)((c0 ^ ((c0 >> 3) & 7)) * 16), gx);
        cp_async16(sb + (unsigned)((c1 ^ ((c1 >> 3) & 7)) * 16), gx + 4);
        asm volatile("cp.async.commit_group;" ::: "memory");
    }

#pragma unroll 1
    for (int i = 0; i < ROWS_PER_BLOCK; i++) {
        const int row = row0 + i;

        asm volatile("cp.async.wait_group 0;" ::: "memory");
        __syncthreads();                  // xbuf[i&1] visible; prior gathers done

        // ---- prefetch next row's x into the other slot ----
        if (i + 1 < ROWS_PER_BLOCK) {
            int rn = row + 1;
            int rr = (rn < batch) ? rn : (batch - 1);
            const float* gx = x + (size_t)rr * 1024 + t * 8;
            unsigned sb = (unsigned)__cvta_generic_to_shared(&xbuf[(i + 1) & 1][0]);
            int c0 = 2 * t, c1 = 2 * t + 1;
            cp_async16(sb + (unsigned)((c0 ^ ((c0 >> 3) & 7)) * 16), gx);
            cp_async16(sb + (unsigned)((c1 ^ ((c1 >> 3) & 7)) * 16), gx + 4);
        }
        asm volatile("cp.async.commit_group;" ::: "memory");

        float v[32];

        // ---- v = x .* B  (swizzled LDS.128, conflict-free) ----
        {
            const float* xs = xbuf[i & 1];
#pragma unroll
            for (int q = 0; q < 8; q++) {
                float4 xv = *reinterpret_cast<const float4*>(
                    xs + 32 * l + 4 * (q ^ (l & 7)));
                v[4*q+0] = xv.x * Bv[4*q+0];
                v[4*q+1] = xv.y * Bv[4*q+1];
                v[4*q+2] = xv.z * Bv[4*q+2];
                v[4*q+3] = xv.w * Bv[4*q+3];
            }
        }

        // ---- FWHT #1, bits 0..4 (packed) ----
        fwht32p(v);

        // ---- transpose A -> B (write 128-bit, read 32-bit) ----
        __syncwarp();
        {
            float4* t4 = reinterpret_cast<float4*>(tb + 36 * l);
#pragma unroll
            for (int q = 0; q < 8; q++)
                t4[q] = make_float4(v[4*q+0], v[4*q+1], v[4*q+2], v[4*q+3]);
        }
        __syncwarp();
#pragma unroll
        for (int k = 0; k < 32; k++) v[k] = tb[36 * k + l];

        // ---- FWHT #1, bits 5..9 (packed) ----
        fwht32p(v);

        // ---- stage to buf: layout-B-linear + swizzle, 8x STS.128 ----
        {
            float* bw = buf + w * 1024;
#pragma unroll
            for (int q = 0; q < 8; q++) {
                int p = 8 * l + (q ^ (l & 7));
                *reinterpret_cast<float4*>(bw + 4 * p) =
                    make_float4(v[4*q+0], v[4*q+1], v[4*q+2], v[4*q+3]);
            }
        }
        __syncthreads();                  // buf fully written

        // ---- permuted gather ∘ G (layout B) ----
#pragma unroll
        for (int k = 0; k < 32; k++) v[k] = buf[pk[k]];
#pragma unroll
        for (int k = 0; k < 32; k++) v[k] *= Gv[k];

        // ---- FWHT #2, bits 5..9 (packed) ----
        fwht32p(v);

        // ---- transpose B -> A (write 32-bit, read 128-bit) ----
        __syncwarp();
#pragma unroll
        for (int k = 0; k < 32; k++) tb[36 * k + l] = v[k];
        __syncwarp();
        {
            const float4* t4 = reinterpret_cast<const float4*>(tb + 36 * l);
#pragma unroll
            for (int q = 0; q < 8; q++) {
                float4 tv = t4[q];
                v[4*q+0] = tv.x; v[4*q+1] = tv.y; v[4*q+2] = tv.z; v[4*q+3] = tv.w;
            }
        }

        // ---- FWHT #2, bits 0..4 (packed) ----
        fwht32p(v);

        // ---- epilogue: S*v + bias, 128-bit store ----
        if (row < batch) {
            float4* o4 = reinterpret_cast<float4*>(out + (size_t)row * 4096 + a0);
#pragma unroll
            for (int q = 0; q < 8; q++) {
                float4 ov;
                ov.x = fmaf(Sv[4*q+0], v[4*q+0], Biv[4*q+0]);
                ov.y = fmaf(Sv[4*q+1], v[4*q+1], Biv[4*q+1]);
                ov.z = fmaf(Sv[4*q+2], v[4*q+2], Biv[4*q+2]);
                ov.w = fmaf(Sv[4*q+3], v[4*q+3], Biv[4*q+3]);
                o4[q] = ov;
            }
        }
    }
}

extern "C" void kernel_launch(void* const* d_in, const int* in_sizes, int n_in,
                              void* d_out, int out_size)
{
    const float* x    = (const float*)d_in[0];   // (16384, 1024) f32
    const float* B    = (const float*)d_in[1];   // (4, 1024) f32
    const float* G    = (const float*)d_in[2];   // (4, 1024) f32
    const float* S    = (const float*)d_in[3];   // (4, 1024) f32
    const float* bias = (const float*)d_in[4];   // (4096,) f32
    const int*   P    = (const int*)d_in[5];     // (4096,) i32
    float* out = (float*)d_out;

    const int batch = in_sizes[0] / 1024;        // 16384
    const int grid  = (batch + ROWS_PER_BLOCK - 1) / ROWS_PER_BLOCK;
    fastfood_kernel<<<grid, 128>>>(x, B, G, S, bias, P, out, batch);
}